// round 11
// baseline (speedup 1.0000x reference)
#include <cuda_runtime.h>
#include <cuda_bf16.h>
#include <cstdint>

// ODEHypernet2D: per-batch hypernetwork MLP, DIMS = [2,256,256,256,2]
// B=64, N=2048. Inputs (metadata order):
//   d_in[0] context [B,N]          f32
//   d_in[1] y       [B,N,2]        f32
//   d_in[2] y_points[B,N,2]        f32
//   d_in[3] target_networks_weights [B, 136716] f32
// Output: [B,N,2] f32
//
// Weight layout per batch (offsets in floats):
//   L0: W[4][256]    @0       bias@1024  ws@1280  bs@1536  sh@1792
//   L1: W[258][256]  @2048    bias@68096 ws@68352 bs@68608 sh@68864
//   L2: W[258][256]  @69120   bias@135168 ws@135424 bs@135680 sh@135936
//   L3: W[258][2]    @136192  bias@136708 ws@136710 bs@136712 sh@136714
// total = 136716

#define B_DIM      64
#define N_DIM      2048
#define TOTAL_W    136716
#define TILE_N     64
#define NPAD       68          // smem row pitch (floats); 272 B -> 16B-aligned rows
#define KBIG       258
#define NPAIR      (TILE_N/2)  // 32 f32x2 accumulators per thread
#define NQUAD      (TILE_N/4)  // 16 LDS.128 per activation row

// ---- packed fp32x2 helpers (sm_100+ PTX) ----
__device__ __forceinline__ unsigned long long pack2(float lo, float hi) {
    unsigned long long r;
    asm("mov.b64 %0, {%1,%2};" : "=l"(r) : "f"(lo), "f"(hi));
    return r;
}
__device__ __forceinline__ void unpack2(unsigned long long v, float& lo, float& hi) {
    asm("mov.b64 {%0,%1}, %2;" : "=f"(lo), "=f"(hi) : "l"(v));
}
__device__ __forceinline__ void ffma2(unsigned long long& d,
                                      unsigned long long a,
                                      unsigned long long b) {
    asm("fma.rn.f32x2 %0, %1, %2, %0;" : "+l"(d) : "l"(a), "l"(b));
}

__device__ __forceinline__ float sigmoidf_(float x) {
    return 1.0f / (1.0f + expf(-x));
}
__device__ __forceinline__ float softplusf_(float x) {
    // log(1 + exp(x)), numerically stable
    return fmaxf(x, 0.0f) + log1pf(expf(-fabsf(x)));
}

// One 256-wide layer: dst[o][n] for o = threadIdx.x (0..255), n in tile.
// src: smem [K][NPAD]. wb: per-batch weight base. woff: W start (floats).
// After W come bias(256), weight_scales(256), bias_scales(256), weight_shift(256).
// Weight LDG for iteration i+1 is hoisted above the FFMA block for iteration i
// so the L2-hit latency (~234-262 cyc) overlaps the ~128-cyc/iter FMA work
// even if ptxas declines to pipeline across the unrolled body.
template<int K, bool SOFTPLUS>
__device__ __forceinline__ void layer256(const float* __restrict__ src,
                                         float* __restrict__ dst,
                                         const float* __restrict__ wb,
                                         int woff,
                                         const float* __restrict__ ctxs,
                                         int t)
{
    unsigned long long acc[NPAIR];
    const unsigned long long z = pack2(0.0f, 0.0f);
#pragma unroll
    for (int p = 0; p < NPAIR; ++p) acc[p] = z;

    const float* __restrict__ Wl = wb + woff + t;   // W[i][t] at Wl[i*256]

    float wcur = Wl[0];
#pragma unroll 2
    for (int i = 0; i < K; ++i) {
        float wnext = (i + 1 < K) ? Wl[(size_t)(i + 1) * 256] : 0.0f;  // prefetch
        unsigned long long w2 = pack2(wcur, wcur);
        // activation row: 16-byte aligned -> LDS.128 (broadcast, conflict-free)
        const ulonglong2* __restrict__ arow =
            (const ulonglong2*)(src + (size_t)i * NPAD);
#pragma unroll
        for (int q = 0; q < NQUAD; ++q) {
            ulonglong2 a4 = arow[q];
            ffma2(acc[2 * q],     a4.x, w2);
            ffma2(acc[2 * q + 1], a4.y, w2);
        }
        wcur = wnext;
    }

    int base = woff + K * 256;
    float bias = wb[base + t];
    float ws   = wb[base + 256 + t];
    float bs   = wb[base + 512 + t];
    float sh   = wb[base + 768 + t];

    float* __restrict__ drow = dst + (size_t)t * NPAD;
#pragma unroll
    for (int p = 0; p < NPAIR; ++p) {
        float v0, v1;
        unpack2(acc[p], v0, v1);
        float c0 = ctxs[2 * p];
        float c1 = ctxs[2 * p + 1];
        v0 = (v0 + bias) * sigmoidf_(fmaf(c0, ws, bs)) + c0 * sh;
        v1 = (v1 + bias) * sigmoidf_(fmaf(c1, ws, bs)) + c1 * sh;
        if (SOFTPLUS) { v0 = softplusf_(v0); v1 = softplusf_(v1); }
        *(float2*)(drow + 2 * p) = make_float2(v0, v1);
    }
}

__global__ void __launch_bounds__(256, 1)
ode_hypernet_kernel(const float* __restrict__ ctx,
                    const float* __restrict__ y,
                    const float* __restrict__ yp,
                    const float* __restrict__ tnw,
                    float* __restrict__ out)
{
    extern __shared__ float smem[];
    float* buf0 = smem;                        // [258][NPAD]
    float* buf1 = smem + KBIG * NPAD;          // [258][NPAD]
    float* ctxs = smem + 2 * KBIG * NPAD;      // [TILE_N]

    const int b  = blockIdx.y;
    const int n0 = blockIdx.x * TILE_N;
    const int t  = threadIdx.x;

    const float* __restrict__ wb = tnw + (size_t)b * TOTAL_W;

    // ---- init: layer-0 input rows (y, y_points) + persistent y_points rows ----
    if (t < TILE_N) {
        size_t gi = (size_t)b * N_DIM + n0 + t;
        float2 yv  = ((const float2*)y)[gi];
        float2 ypv = ((const float2*)yp)[gi];
        ctxs[t] = ctx[gi];
        buf0[0 * NPAD + t] = yv.x;
        buf0[1 * NPAD + t] = yv.y;
        buf0[2 * NPAD + t] = ypv.x;
        buf0[3 * NPAD + t] = ypv.y;
        buf0[256 * NPAD + t] = ypv.x;   // concat columns for layer-2 input
        buf0[257 * NPAD + t] = ypv.y;
        buf1[256 * NPAD + t] = ypv.x;   // concat columns for layer-1/3 input
        buf1[257 * NPAD + t] = ypv.y;
    }
    __syncthreads();

    // L0: buf0[4 rows] -> buf1, softplus
    layer256<4, true>(buf0, buf1, wb, 0, ctxs, t);
    __syncthreads();
    // L1: buf1[258 rows] -> buf0, softplus
    layer256<KBIG, true>(buf1, buf0, wb, 2048, ctxs, t);
    __syncthreads();
    // L2: buf0 -> buf1, softplus
    layer256<KBIG, true>(buf0, buf1, wb, 69120, ctxs, t);
    __syncthreads();

    // L3: 258 -> 2, no softplus. Threads 0..63, one point each.
    if (t < TILE_N) {
        float a0 = 0.0f, a1 = 0.0f;
        const float* __restrict__ W3 = wb + 136192;
#pragma unroll 4
        for (int i = 0; i < KBIG; ++i) {
            float a = buf1[(size_t)i * NPAD + t];
            a0 = fmaf(a, W3[2 * i],     a0);
            a1 = fmaf(a, W3[2 * i + 1], a1);
        }
        float c   = ctxs[t];
        float b0  = wb[136708], b1  = wb[136709];
        float ws0 = wb[136710], ws1 = wb[136711];
        float bs0 = wb[136712], bs1 = wb[136713];
        float sh0 = wb[136714], sh1 = wb[136715];
        float v0 = (a0 + b0) * sigmoidf_(fmaf(c, ws0, bs0)) + c * sh0;
        float v1 = (a1 + b1) * sigmoidf_(fmaf(c, ws1, bs1)) + c * sh1;
        ((float2*)out)[(size_t)b * N_DIM + n0 + t] = make_float2(v0, v1);
    }
}

extern "C" void kernel_launch(void* const* d_in, const int* in_sizes, int n_in,
                              void* d_out, int out_size)
{
    const float* ctx = (const float*)d_in[0];
    const float* y   = (const float*)d_in[1];
    const float* yp  = (const float*)d_in[2];
    const float* tnw = (const float*)d_in[3];
    float* out = (float*)d_out;

    const int smem_bytes = (2 * KBIG * NPAD + TILE_N) * (int)sizeof(float); // 140,608 B
    cudaFuncSetAttribute(ode_hypernet_kernel,
                         cudaFuncAttributeMaxDynamicSharedMemorySize, smem_bytes);

    dim3 grid(N_DIM / TILE_N, B_DIM);   // (32, 64) = 2048 CTAs
    ode_hypernet_kernel<<<grid, 256, smem_bytes>>>(ctx, y, yp, tnw, out);
}